// round 1
// baseline (speedup 1.0000x reference)
#include <cuda_runtime.h>
#include <cuda_bf16.h>
#include <mma.h>
#include <math.h>
#include <stdint.h>

using namespace nvcuda;

#define B_TOK 8192
#define H_DIM 1024
#define N_EXP 8

// ---------------- scratch (static device memory; no allocations) ----------------
__device__ __nv_bfloat16 g_x_hi[B_TOK * H_DIM];
__device__ __nv_bfloat16 g_x_lo[B_TOK * H_DIM];
__device__ __nv_bfloat16 g_w_hi[N_EXP * H_DIM * H_DIM];
__device__ __nv_bfloat16 g_w_lo[N_EXP * H_DIM * H_DIM];

__device__ int   g_tok_e[B_TOK * 2];
__device__ float g_tok_w[B_TOK * 2];
__device__ int   g_counts[N_EXP];
__device__ int   g_cursor[N_EXP];
__device__ int   g_poff[N_EXP + 1];     // 64-aligned padded segment offsets
__device__ int   g_tileoff[N_EXP + 1];  // tile offsets (tiles of 64 rows)
__device__ int   g_rows_tok[16896];     // padded permutation: row -> token
__device__ int   g_pos[B_TOK * 2];      // token,slot -> row in ybuf
__device__ float g_ybuf[16896 * H_DIM]; // per-(token,expert) GEMM output rows

// ---------------- init ----------------
__global__ void init_kernel() {
    int t = threadIdx.x;
    if (t < N_EXP) { g_counts[t] = 0; g_cursor[t] = 0; }
}

// ---------------- fp32 -> bf16 hi/lo split (x and expert_w: both 8388608 elems) ----------------
__global__ void convert_kernel(const float* __restrict__ x, const float* __restrict__ w) {
    const int n4 = (B_TOK * H_DIM) / 4;   // 2097152 (same for both tensors)
    const int stride = gridDim.x * blockDim.x;
    for (int j = blockIdx.x * blockDim.x + threadIdx.x; j < n4; j += stride) {
        float4 v = reinterpret_cast<const float4*>(x)[j];
        __nv_bfloat16 h0 = __float2bfloat16(v.x);
        __nv_bfloat16 h1 = __float2bfloat16(v.y);
        __nv_bfloat16 h2 = __float2bfloat16(v.z);
        __nv_bfloat16 h3 = __float2bfloat16(v.w);
        __nv_bfloat16 l0 = __float2bfloat16(v.x - __bfloat162float(h0));
        __nv_bfloat16 l1 = __float2bfloat16(v.y - __bfloat162float(h1));
        __nv_bfloat16 l2 = __float2bfloat16(v.z - __bfloat162float(h2));
        __nv_bfloat16 l3 = __float2bfloat16(v.w - __bfloat162float(h3));
        __nv_bfloat162 p;
        p.x = h0; p.y = h1; reinterpret_cast<__nv_bfloat162*>(g_x_hi)[2 * j] = p;
        p.x = h2; p.y = h3; reinterpret_cast<__nv_bfloat162*>(g_x_hi)[2 * j + 1] = p;
        p.x = l0; p.y = l1; reinterpret_cast<__nv_bfloat162*>(g_x_lo)[2 * j] = p;
        p.x = l2; p.y = l3; reinterpret_cast<__nv_bfloat162*>(g_x_lo)[2 * j + 1] = p;

        float4 u = reinterpret_cast<const float4*>(w)[j];
        h0 = __float2bfloat16(u.x);
        h1 = __float2bfloat16(u.y);
        h2 = __float2bfloat16(u.z);
        h3 = __float2bfloat16(u.w);
        l0 = __float2bfloat16(u.x - __bfloat162float(h0));
        l1 = __float2bfloat16(u.y - __bfloat162float(h1));
        l2 = __float2bfloat16(u.z - __bfloat162float(h2));
        l3 = __float2bfloat16(u.w - __bfloat162float(h3));
        p.x = h0; p.y = h1; reinterpret_cast<__nv_bfloat162*>(g_w_hi)[2 * j] = p;
        p.x = h2; p.y = h3; reinterpret_cast<__nv_bfloat162*>(g_w_hi)[2 * j + 1] = p;
        p.x = l0; p.y = l1; reinterpret_cast<__nv_bfloat162*>(g_w_lo)[2 * j] = p;
        p.x = l2; p.y = l3; reinterpret_cast<__nv_bfloat162*>(g_w_lo)[2 * j + 1] = p;
    }
}

// ---------------- gate: logits, top-2, softmax, counts ----------------
__global__ void gate_kernel(const float* __restrict__ x, const float* __restrict__ gw) {
    __shared__ float sgw[N_EXP * H_DIM];  // transposed [e][h]
    int tid = threadIdx.x;
    for (int i = tid; i < N_EXP * H_DIM; i += blockDim.x) {
        int h = i >> 3, e = i & 7;
        sgw[e * H_DIM + h] = gw[i];
    }
    __syncthreads();

    int warp = tid >> 5, lane = tid & 31;
    int b = blockIdx.x * 8 + warp;
    const float* xr = x + (size_t)b * H_DIM;

    float acc[N_EXP];
#pragma unroll
    for (int e = 0; e < N_EXP; e++) acc[e] = 0.0f;

    for (int i = lane; i < H_DIM; i += 32) {
        float xv = xr[i];
#pragma unroll
        for (int e = 0; e < N_EXP; e++) acc[e] += xv * sgw[e * H_DIM + i];
    }
#pragma unroll
    for (int e = 0; e < N_EXP; e++) {
#pragma unroll
        for (int o = 16; o > 0; o >>= 1)
            acc[e] += __shfl_down_sync(0xffffffffu, acc[e], o);
    }
    if (lane == 0) {
        float b1v = -1e30f; int b1 = 0;
#pragma unroll
        for (int e = 0; e < N_EXP; e++)
            if (acc[e] > b1v) { b1v = acc[e]; b1 = e; }
        float b2v = -1e30f; int b2 = 0;
#pragma unroll
        for (int e = 0; e < N_EXP; e++)
            if (e != b1 && acc[e] > b2v) { b2v = acc[e]; b2 = e; }
        float e2 = expf(b2v - b1v);
        float inv = 1.0f / (1.0f + e2);
        g_tok_e[2 * b]     = b1;
        g_tok_e[2 * b + 1] = b2;
        g_tok_w[2 * b]     = inv;
        g_tok_w[2 * b + 1] = e2 * inv;
        atomicAdd(&g_counts[b1], 1);
        atomicAdd(&g_counts[b2], 1);
    }
}

// ---------------- scan: padded offsets + tile offsets ----------------
__global__ void scan_kernel() {
    if (threadIdx.x == 0) {
        int po = 0, to = 0;
        for (int e = 0; e < N_EXP; e++) {
            g_poff[e] = po;
            g_tileoff[e] = to;
            int t = (g_counts[e] + 63) >> 6;
            to += t;
            po += t << 6;
        }
        g_poff[N_EXP] = po;
        g_tileoff[N_EXP] = to;
    }
}

// ---------------- scatter: build permutation + inverse position map ----------------
__global__ void scatter_kernel() {
    int b = blockIdx.x * blockDim.x + threadIdx.x;
    if (b >= B_TOK) return;
#pragma unroll
    for (int j = 0; j < 2; j++) {
        int e = g_tok_e[2 * b + j];
        int p = g_poff[e] + atomicAdd(&g_cursor[e], 1);
        g_rows_tok[p] = b;
        g_pos[2 * b + j] = p;
    }
}

// ---------------- grouped GEMM: 64x64 tile, bf16x3 split, wmma m16n16k16 ----------------
__global__ __launch_bounds__(256) void gemm_kernel() {
    int mt = blockIdx.x;
    if (mt >= g_tileoff[N_EXP]) return;
    int nt = blockIdx.y;
    int e = 0;
    while (mt >= g_tileoff[e + 1]) e++;
    int row0 = g_poff[e] + ((mt - g_tileoff[e]) << 6);
    int n0 = nt << 6;

    __shared__ __nv_bfloat16 sAh[64 * 72];
    __shared__ __nv_bfloat16 sAl[64 * 72];
    __shared__ __nv_bfloat16 sBh[64 * 72];
    __shared__ __nv_bfloat16 sBl[64 * 72];
    __shared__ int s_tok[64];

    int tid = threadIdx.x;
    if (tid < 64) s_tok[tid] = g_rows_tok[row0 + tid];
    __syncthreads();

    int warp = tid >> 5;
    int wm = warp & 3;   // 4 m-strips of 16
    int wn = warp >> 2;  // 2 n-strips of 32

    wmma::fragment<wmma::accumulator, 16, 16, 16, float> acc[2];
    wmma::fill_fragment(acc[0], 0.0f);
    wmma::fill_fragment(acc[1], 0.0f);

    const __nv_bfloat16* wbh = g_w_hi + (size_t)e * (H_DIM * H_DIM) + n0;
    const __nv_bfloat16* wbl = g_w_lo + (size_t)e * (H_DIM * H_DIM) + n0;

    for (int k0 = 0; k0 < H_DIM; k0 += 64) {
        for (int i = tid; i < 512; i += 256) {
            int r = i >> 3, c = i & 7;
            int tok = s_tok[r];
            const uint4* pxh = reinterpret_cast<const uint4*>(g_x_hi + (size_t)tok * H_DIM + k0);
            const uint4* pxl = reinterpret_cast<const uint4*>(g_x_lo + (size_t)tok * H_DIM + k0);
            reinterpret_cast<uint4*>(sAh + r * 72)[c] = pxh[c];
            reinterpret_cast<uint4*>(sAl + r * 72)[c] = pxl[c];
            const uint4* pbh = reinterpret_cast<const uint4*>(wbh + (size_t)(k0 + r) * H_DIM);
            const uint4* pbl = reinterpret_cast<const uint4*>(wbl + (size_t)(k0 + r) * H_DIM);
            reinterpret_cast<uint4*>(sBh + r * 72)[c] = pbh[c];
            reinterpret_cast<uint4*>(sBl + r * 72)[c] = pbl[c];
        }
        __syncthreads();
#pragma unroll
        for (int ks = 0; ks < 4; ks++) {
            wmma::fragment<wmma::matrix_a, 16, 16, 16, __nv_bfloat16, wmma::row_major> ah, al;
            wmma::fragment<wmma::matrix_b, 16, 16, 16, __nv_bfloat16, wmma::row_major> bf;
            wmma::load_matrix_sync(ah, sAh + (wm * 16) * 72 + ks * 16, 72);
            wmma::load_matrix_sync(al, sAl + (wm * 16) * 72 + ks * 16, 72);
#pragma unroll
            for (int j = 0; j < 2; j++) {
                wmma::load_matrix_sync(bf, sBh + (ks * 16) * 72 + wn * 32 + j * 16, 72);
                wmma::mma_sync(acc[j], ah, bf, acc[j]);   // xh * wh
                wmma::mma_sync(acc[j], al, bf, acc[j]);   // xl * wh
                wmma::load_matrix_sync(bf, sBl + (ks * 16) * 72 + wn * 32 + j * 16, 72);
                wmma::mma_sync(acc[j], ah, bf, acc[j]);   // xh * wl
            }
        }
        __syncthreads();
    }

    float* yb = g_ybuf + (size_t)(row0 + wm * 16) * H_DIM + n0 + wn * 32;
    wmma::store_matrix_sync(yb, acc[0], H_DIM, wmma::mem_row_major);
    wmma::store_matrix_sync(yb + 16, acc[1], H_DIM, wmma::mem_row_major);
}

// ---------------- combine: out[b] = w0*y[p0] + w1*y[p1] ----------------
__global__ void combine_kernel(float* __restrict__ out) {
    int gid = blockIdx.x * blockDim.x + threadIdx.x;  // over B_TOK * 256 float4
    int b = gid >> 8;
    int c4 = gid & 255;
    float w0 = g_tok_w[2 * b];
    float w1 = g_tok_w[2 * b + 1];
    int p0 = g_pos[2 * b];
    int p1 = g_pos[2 * b + 1];
    float4 y0 = reinterpret_cast<const float4*>(g_ybuf + (size_t)p0 * H_DIM)[c4];
    float4 y1 = reinterpret_cast<const float4*>(g_ybuf + (size_t)p1 * H_DIM)[c4];
    float4 o;
    o.x = w0 * y0.x + w1 * y1.x;
    o.y = w0 * y0.y + w1 * y1.y;
    o.z = w0 * y0.z + w1 * y1.z;
    o.w = w0 * y0.w + w1 * y1.w;
    reinterpret_cast<float4*>(out + (size_t)b * H_DIM)[c4] = o;
}

// ---------------- launch ----------------
extern "C" void kernel_launch(void* const* d_in, const int* in_sizes, int n_in,
                              void* d_out, int out_size) {
    const float* x  = (const float*)d_in[0];
    const float* gw = (const float*)d_in[1];
    const float* ew = (const float*)d_in[2];
    float* out = (float*)d_out;

    init_kernel<<<1, 32>>>();
    convert_kernel<<<2048, 256>>>(x, ew);
    gate_kernel<<<1024, 256>>>(x, gw);
    scan_kernel<<<1, 1>>>();
    scatter_kernel<<<32, 256>>>();
    gemm_kernel<<<dim3(264, 16), 256>>>();
    combine_kernel<<<8192, 256>>>(out);
}

// round 3
// speedup vs baseline: 2.4225x; 2.4225x over previous
#include <cuda_runtime.h>
#include <cuda_fp16.h>
#include <mma.h>
#include <math.h>
#include <stdint.h>

using namespace nvcuda;

#define B_TOK 8192
#define H_DIM 1024
#define N_EXP 8
#define MAX_ROWS 17536   // 137 tiles * 128

// ---------------- scratch (static device memory; no allocations) ----------------
__device__ __half g_x_f16[B_TOK * H_DIM];
__device__ __half g_w_f16[N_EXP * H_DIM * H_DIM];   // [e][k][n] native layout

__device__ int   g_tok_e[B_TOK * 2];
__device__ float g_tok_w[B_TOK * 2];
__device__ int   g_counts[N_EXP];
__device__ int   g_cursor[N_EXP];
__device__ int   g_poff[N_EXP + 1];     // 128-aligned padded segment offsets
__device__ int   g_tileoff[N_EXP + 1];  // tile offsets (tiles of 128 rows)
__device__ int   g_rows_tok[MAX_ROWS];  // padded permutation: row -> token
__device__ int   g_pos[B_TOK * 2];      // token,slot -> row in ybuf
__device__ float g_ybuf[(size_t)MAX_ROWS * H_DIM];

// ---------------- cp.async helpers ----------------
#define CP_ASYNC16(dst, src) \
    asm volatile("cp.async.cg.shared.global [%0], [%1], 16;\n" :: "r"(dst), "l"(src))
#define CP_COMMIT() asm volatile("cp.async.commit_group;\n" ::: "memory")
#define CP_WAIT(n)  asm volatile("cp.async.wait_group %0;\n" :: "n"(n) : "memory")

__device__ __forceinline__ uint32_t smem_u32(const void* p) {
    uint32_t a;
    asm("{ .reg .u64 t; cvta.to.shared.u64 t, %1; cvt.u32.u64 %0, t; }" : "=r"(a) : "l"(p));
    return a;
}

// ---------------- init ----------------
__global__ void init_kernel() {
    int t = blockIdx.x * blockDim.x + threadIdx.x;
    if (t < N_EXP) { g_counts[t] = 0; g_cursor[t] = 0; }
    if (t < MAX_ROWS) g_rows_tok[t] = 0;
}

// ---------------- fp32 -> fp16 convert (x: 8M elems, w: 8M elems) ----------------
__global__ void convert_kernel(const float* __restrict__ x, const float* __restrict__ w) {
    const int n4 = (B_TOK * H_DIM) / 4;   // 2M float4 for each tensor
    const int stride = gridDim.x * blockDim.x;
    for (int j = blockIdx.x * blockDim.x + threadIdx.x; j < n4; j += stride) {
        float4 v = reinterpret_cast<const float4*>(x)[j];
        __half2 p0 = __floats2half2_rn(v.x, v.y);
        __half2 p1 = __floats2half2_rn(v.z, v.w);
        reinterpret_cast<__half2*>(g_x_f16)[2 * j]     = p0;
        reinterpret_cast<__half2*>(g_x_f16)[2 * j + 1] = p1;

        float4 u = reinterpret_cast<const float4*>(w)[j];
        p0 = __floats2half2_rn(u.x, u.y);
        p1 = __floats2half2_rn(u.z, u.w);
        reinterpret_cast<__half2*>(g_w_f16)[2 * j]     = p0;
        reinterpret_cast<__half2*>(g_w_f16)[2 * j + 1] = p1;
    }
}

// ---------------- gate: logits, top-2, softmax, counts ----------------
__global__ void gate_kernel(const float* __restrict__ x, const float* __restrict__ gw) {
    __shared__ float sgw[N_EXP * H_DIM];  // transposed [e][h]
    int tid = threadIdx.x;
    for (int i = tid; i < N_EXP * H_DIM; i += blockDim.x) {
        int h = i >> 3, e = i & 7;
        sgw[e * H_DIM + h] = gw[i];
    }
    __syncthreads();
    int warp = tid >> 5, lane = tid & 31;
    int b = blockIdx.x * 8 + warp;
    const float* xr = x + (size_t)b * H_DIM;
    float acc[N_EXP];
#pragma unroll
    for (int e = 0; e < N_EXP; e++) acc[e] = 0.0f;
    for (int i = lane; i < H_DIM; i += 32) {
        float xv = xr[i];
#pragma unroll
        for (int e = 0; e < N_EXP; e++) acc[e] += xv * sgw[e * H_DIM + i];
    }
#pragma unroll
    for (int e = 0; e < N_EXP; e++) {
#pragma unroll
        for (int o = 16; o > 0; o >>= 1)
            acc[e] += __shfl_down_sync(0xffffffffu, acc[e], o);
    }
    if (lane == 0) {
        float b1v = -1e30f; int b1 = 0;
#pragma unroll
        for (int e = 0; e < N_EXP; e++)
            if (acc[e] > b1v) { b1v = acc[e]; b1 = e; }
        float b2v = -1e30f; int b2 = 0;
#pragma unroll
        for (int e = 0; e < N_EXP; e++)
            if (e != b1 && acc[e] > b2v) { b2v = acc[e]; b2 = e; }
        float e2 = expf(b2v - b1v);
        float inv = 1.0f / (1.0f + e2);
        g_tok_e[2 * b]     = b1;
        g_tok_e[2 * b + 1] = b2;
        g_tok_w[2 * b]     = inv;
        g_tok_w[2 * b + 1] = e2 * inv;
        atomicAdd(&g_counts[b1], 1);
        atomicAdd(&g_counts[b2], 1);
    }
}

// ---------------- scan (128-row padded segments) ----------------
__global__ void scan_kernel() {
    if (threadIdx.x == 0) {
        int po = 0, to = 0;
        for (int e = 0; e < N_EXP; e++) {
            g_poff[e] = po;
            g_tileoff[e] = to;
            int t = (g_counts[e] + 127) >> 7;
            to += t;
            po += t << 7;
        }
        g_poff[N_EXP] = po;
        g_tileoff[N_EXP] = to;
    }
}

// ---------------- scatter ----------------
__global__ void scatter_kernel() {
    int b = blockIdx.x * blockDim.x + threadIdx.x;
    if (b >= B_TOK) return;
#pragma unroll
    for (int j = 0; j < 2; j++) {
        int e = g_tok_e[2 * b + j];
        int p = g_poff[e] + atomicAdd(&g_cursor[e], 1);
        g_rows_tok[p] = b;
        g_pos[2 * b + j] = p;
    }
}

// ---------------- grouped GEMM: 128x128 tile, fp16 wmma, cp.async double-buffered ----------------
// dynamic smem (halves): sA[2][128][72], sB[2][64][136], then s_tok[128] ints
#define SA_LD 72
#define SB_LD 136
#define SA_ST (128 * SA_LD)          // 9216 halves per stage
#define SB_ST (64 * SB_LD)           // 8704 halves per stage
#define SB_BASE (2 * SA_ST)          // halves offset
#define TOK_BASE_B ((2 * SA_ST + 2 * SB_ST) * 2)  // byte offset of s_tok
#define SMEM_TOTAL (TOK_BASE_B + 512)

__global__ __launch_bounds__(256, 2) void gemm_f16_kernel() {
    int mt = blockIdx.x;
    if (mt >= g_tileoff[N_EXP]) return;
    int e = 0;
    while (mt >= g_tileoff[e + 1]) e++;
    int row0 = g_poff[e] + ((mt - g_tileoff[e]) << 7);
    int n0 = blockIdx.y << 7;

    extern __shared__ char smem[];
    __half* sA = reinterpret_cast<__half*>(smem);
    __half* sB = reinterpret_cast<__half*>(smem) + SB_BASE;
    int* s_tok = reinterpret_cast<int*>(smem + TOK_BASE_B);
    uint32_t sbase = smem_u32(smem);

    int tid = threadIdx.x;
    if (tid < 128) s_tok[tid] = g_rows_tok[row0 + tid];
    __syncthreads();

    const __half* wbase = g_w_f16 + (size_t)e * H_DIM * H_DIM + n0;

    // issue async loads for stage st covering k-range [k0, k0+64)
    auto do_load = [&](int st, int k0) {
        uint32_t aoff = sbase + (uint32_t)(st * SA_ST * 2);
        uint32_t boff = sbase + (uint32_t)((SB_BASE + st * SB_ST) * 2);
#pragma unroll
        for (int ii = 0; ii < 4; ii++) {
            int idx = tid + ii * 256;           // 0..1023
            // A: 128 rows x 8 chunks of 16B
            int ra = idx >> 3, ca = idx & 7;
            const char* asrc = (const char*)(g_x_f16 + (size_t)s_tok[ra] * H_DIM + k0) + ca * 16;
            CP_ASYNC16(aoff + (uint32_t)(ra * SA_LD + ca * 8) * 2, asrc);
            // B: 64 rows x 16 chunks of 16B
            int rb = idx >> 4, cb = idx & 15;
            const char* bsrc = (const char*)(wbase + (size_t)(k0 + rb) * H_DIM) + cb * 16;
            CP_ASYNC16(boff + (uint32_t)(rb * SB_LD + cb * 8) * 2, bsrc);
        }
        CP_COMMIT();
    };

    int wid = tid >> 5;
    int wm = wid & 3;   // 4 m-strips of 32 rows
    int wn = wid >> 2;  // 2 n-strips of 64 cols

    wmma::fragment<wmma::accumulator, 16, 16, 16, float> acc[2][4];
#pragma unroll
    for (int f = 0; f < 2; f++)
#pragma unroll
        for (int j = 0; j < 4; j++) wmma::fill_fragment(acc[f][j], 0.0f);

    do_load(0, 0);
    do_load(1, 64);

    for (int it = 0; it < 16; it++) {
        int st = it & 1;
        if (it == 15) { CP_WAIT(0); } else { CP_WAIT(1); }
        __syncthreads();

        const __half* A0 = sA + st * SA_ST + (wm * 32) * SA_LD;
        const __half* B0 = sB + st * SB_ST + wn * 64;
#pragma unroll
        for (int ks = 0; ks < 4; ks++) {
            wmma::fragment<wmma::matrix_a, 16, 16, 16, __half, wmma::row_major> af[2];
            wmma::load_matrix_sync(af[0], A0 + ks * 16, SA_LD);
            wmma::load_matrix_sync(af[1], A0 + 16 * SA_LD + ks * 16, SA_LD);
#pragma unroll
            for (int j = 0; j < 4; j++) {
                wmma::fragment<wmma::matrix_b, 16, 16, 16, __half, wmma::row_major> bf;
                wmma::load_matrix_sync(bf, B0 + (ks * 16) * SB_LD + j * 16, SB_LD);
                wmma::mma_sync(acc[0][j], af[0], bf, acc[0][j]);
                wmma::mma_sync(acc[1][j], af[1], bf, acc[1][j]);
            }
        }
        __syncthreads();
        if (it + 2 < 16) do_load(st, (it + 2) << 6);
    }

    // epilogue: store 32x64 per warp
    float* yb = g_ybuf + (size_t)(row0 + wm * 32) * H_DIM + n0 + wn * 64;
#pragma unroll
    for (int f = 0; f < 2; f++)
#pragma unroll
        for (int j = 0; j < 4; j++)
            wmma::store_matrix_sync(yb + (size_t)(f * 16) * H_DIM + j * 16,
                                    acc[f][j], H_DIM, wmma::mem_row_major);
}

// ---------------- combine: out[b] = w0*y[p0] + w1*y[p1] ----------------
__global__ void combine_kernel(float* __restrict__ out) {
    int gid = blockIdx.x * blockDim.x + threadIdx.x;
    int b = gid >> 8;
    int c4 = gid & 255;
    float w0 = g_tok_w[2 * b];
    float w1 = g_tok_w[2 * b + 1];
    int p0 = g_pos[2 * b];
    int p1 = g_pos[2 * b + 1];
    float4 y0 = reinterpret_cast<const float4*>(g_ybuf + (size_t)p0 * H_DIM)[c4];
    float4 y1 = reinterpret_cast<const float4*>(g_ybuf + (size_t)p1 * H_DIM)[c4];
    float4 o;
    o.x = w0 * y0.x + w1 * y1.x;
    o.y = w0 * y0.y + w1 * y1.y;
    o.z = w0 * y0.z + w1 * y1.z;
    o.w = w0 * y0.w + w1 * y1.w;
    reinterpret_cast<float4*>(out + (size_t)b * H_DIM)[c4] = o;
}

// ---------------- launch ----------------
extern "C" void kernel_launch(void* const* d_in, const int* in_sizes, int n_in,
                              void* d_out, int out_size) {
    const float* x  = (const float*)d_in[0];
    const float* gw = (const float*)d_in[1];
    const float* ew = (const float*)d_in[2];
    float* out = (float*)d_out;

    cudaFuncSetAttribute(gemm_f16_kernel, cudaFuncAttributeMaxDynamicSharedMemorySize, SMEM_TOTAL);

    init_kernel<<<69, 256>>>();
    convert_kernel<<<2048, 256>>>(x, ew);
    gate_kernel<<<1024, 256>>>(x, gw);
    scan_kernel<<<1, 1>>>();
    scatter_kernel<<<32, 256>>>();
    gemm_f16_kernel<<<dim3(137, 8), 256, SMEM_TOTAL>>>();
    combine_kernel<<<8192, 256>>>(out);
}

// round 4
// speedup vs baseline: 3.6027x; 1.4872x over previous
#include <cuda_runtime.h>
#include <cuda_fp16.h>
#include <mma.h>
#include <math.h>
#include <stdint.h>

using namespace nvcuda;

#define B_TOK 8192
#define H_DIM 1024
#define N_EXP 8
#define MAX_ROWS 17536   // 137 tiles * 128

// ---------------- scratch (static device memory; no allocations) ----------------
__device__ __half g_x_f16[B_TOK * H_DIM];
__device__ __half g_w_f16[N_EXP * H_DIM * H_DIM];   // [e][k][n] native layout

__device__ int   g_tok_e[B_TOK * 2];
__device__ float g_tok_w[B_TOK * 2];
__device__ int   g_counts[N_EXP];
__device__ int   g_cursor[N_EXP];
__device__ int   g_poff[N_EXP + 1];     // 128-aligned padded segment offsets
__device__ int   g_tileoff[N_EXP + 1];  // tile offsets (tiles of 128 rows)
__device__ int   g_rows_tok[MAX_ROWS];  // padded permutation: row -> token
__device__ int   g_pos[B_TOK * 2];      // token,slot -> row in ybuf
__device__ float g_ybuf[(size_t)MAX_ROWS * H_DIM];

// ---------------- cp.async helpers ----------------
#define CP_ASYNC16(dst, src) \
    asm volatile("cp.async.cg.shared.global [%0], [%1], 16;\n" :: "r"(dst), "l"(src))
#define CP_COMMIT() asm volatile("cp.async.commit_group;\n" ::: "memory")
#define CP_WAIT(n)  asm volatile("cp.async.wait_group %0;\n" :: "n"(n) : "memory")

__device__ __forceinline__ uint32_t smem_u32(const void* p) {
    uint32_t a;
    asm("{ .reg .u64 t; cvta.to.shared.u64 t, %1; cvt.u32.u64 %0, t; }" : "=r"(a) : "l"(p));
    return a;
}

// ---------------- convert (fp32 -> fp16, x and w) + init fold ----------------
__global__ void convert_kernel(const float* __restrict__ x, const float* __restrict__ w) {
    int gid = blockIdx.x * blockDim.x + threadIdx.x;
    // folded init (runs long before gate/scatter/gemm launches)
    if (gid < N_EXP) { g_counts[gid] = 0; g_cursor[gid] = 0; }
    if (gid < MAX_ROWS) g_rows_tok[gid] = 0;

    const int n4 = (B_TOK * H_DIM) / 4;   // 2M float4 for each tensor
    const int stride = gridDim.x * blockDim.x;
    for (int j = gid; j < n4; j += stride) {
        float4 v = reinterpret_cast<const float4*>(x)[j];
        __half2 p0 = __floats2half2_rn(v.x, v.y);
        __half2 p1 = __floats2half2_rn(v.z, v.w);
        reinterpret_cast<__half2*>(g_x_f16)[2 * j]     = p0;
        reinterpret_cast<__half2*>(g_x_f16)[2 * j + 1] = p1;

        float4 u = reinterpret_cast<const float4*>(w)[j];
        p0 = __floats2half2_rn(u.x, u.y);
        p1 = __floats2half2_rn(u.z, u.w);
        reinterpret_cast<__half2*>(g_w_f16)[2 * j]     = p0;
        reinterpret_cast<__half2*>(g_w_f16)[2 * j + 1] = p1;
    }
}

// ---------------- gate: logits, top-2, softmax, counts ----------------
__global__ void gate_kernel(const float* __restrict__ x, const float* __restrict__ gw) {
    __shared__ float sgw[N_EXP * H_DIM];  // transposed [e][h]
    int tid = threadIdx.x;
    for (int i = tid; i < N_EXP * H_DIM; i += blockDim.x) {
        int h = i >> 3, e = i & 7;
        sgw[e * H_DIM + h] = gw[i];
    }
    __syncthreads();
    int warp = tid >> 5, lane = tid & 31;
    int b = blockIdx.x * 8 + warp;
    const float* xr = x + (size_t)b * H_DIM;
    float acc[N_EXP];
#pragma unroll
    for (int e = 0; e < N_EXP; e++) acc[e] = 0.0f;
    for (int i = lane; i < H_DIM; i += 32) {
        float xv = xr[i];
#pragma unroll
        for (int e = 0; e < N_EXP; e++) acc[e] += xv * sgw[e * H_DIM + i];
    }
#pragma unroll
    for (int e = 0; e < N_EXP; e++) {
#pragma unroll
        for (int o = 16; o > 0; o >>= 1)
            acc[e] += __shfl_down_sync(0xffffffffu, acc[e], o);
    }
    if (lane == 0) {
        float b1v = -1e30f; int b1 = 0;
#pragma unroll
        for (int e = 0; e < N_EXP; e++)
            if (acc[e] > b1v) { b1v = acc[e]; b1 = e; }
        float b2v = -1e30f; int b2 = 0;
#pragma unroll
        for (int e = 0; e < N_EXP; e++)
            if (e != b1 && acc[e] > b2v) { b2v = acc[e]; b2 = e; }
        float e2 = expf(b2v - b1v);
        float inv = 1.0f / (1.0f + e2);
        g_tok_e[2 * b]     = b1;
        g_tok_e[2 * b + 1] = b2;
        g_tok_w[2 * b]     = inv;
        g_tok_w[2 * b + 1] = e2 * inv;
        atomicAdd(&g_counts[b1], 1);
        atomicAdd(&g_counts[b2], 1);
    }
}

// ---------------- scatter (scan folded in: every block recomputes the 8-entry prefix) ----------------
__global__ void scatter_kernel() {
    __shared__ int s_poff[N_EXP + 1];
    if (threadIdx.x == 0) {
        int po = 0, to = 0;
        int poff[N_EXP + 1], tilo[N_EXP + 1];
        for (int e = 0; e < N_EXP; e++) {
            poff[e] = po; tilo[e] = to;
            int t = (g_counts[e] + 127) >> 7;
            to += t;
            po += t << 7;
        }
        poff[N_EXP] = po; tilo[N_EXP] = to;
        for (int e = 0; e <= N_EXP; e++) s_poff[e] = poff[e];
        if (blockIdx.x == 0) {   // publish for gemm/combine (identical values from any block)
            for (int e = 0; e <= N_EXP; e++) { g_poff[e] = poff[e]; g_tileoff[e] = tilo[e]; }
        }
    }
    __syncthreads();
    int b = blockIdx.x * blockDim.x + threadIdx.x;
    if (b >= B_TOK) return;
#pragma unroll
    for (int j = 0; j < 2; j++) {
        int e = g_tok_e[2 * b + j];
        int p = s_poff[e] + atomicAdd(&g_cursor[e], 1);
        g_rows_tok[p] = b;
        g_pos[2 * b + j] = p;
    }
}

// ---------------- grouped GEMM: 128x128 tile, fp16 wmma, 3-stage cp.async ----------------
// dynamic smem (halves): sA[3][128][72], sB[3][64][136], then s_tok[128] ints
#define N_STAGE 3
#define SA_LD 72
#define SB_LD 136
#define SA_ST (128 * SA_LD)          // 9216 halves per stage
#define SB_ST (64 * SB_LD)           // 8704 halves per stage
#define SB_BASE (N_STAGE * SA_ST)    // halves offset
#define TOK_BASE_B ((N_STAGE * SA_ST + N_STAGE * SB_ST) * 2)  // byte offset of s_tok
#define SMEM_TOTAL (TOK_BASE_B + 512)

__global__ __launch_bounds__(256, 2) void gemm_f16_kernel() {
    int mt = blockIdx.x;
    if (mt >= g_tileoff[N_EXP]) return;
    int e = 0;
    while (mt >= g_tileoff[e + 1]) e++;
    int row0 = g_poff[e] + ((mt - g_tileoff[e]) << 7);
    int n0 = blockIdx.y << 7;

    extern __shared__ char smem[];
    __half* sA = reinterpret_cast<__half*>(smem);
    __half* sB = reinterpret_cast<__half*>(smem) + SB_BASE;
    int* s_tok = reinterpret_cast<int*>(smem + TOK_BASE_B);
    uint32_t sbase = smem_u32(smem);

    int tid = threadIdx.x;
    if (tid < 128) s_tok[tid] = g_rows_tok[row0 + tid];
    __syncthreads();

    const __half* wbase = g_w_f16 + (size_t)e * H_DIM * H_DIM + n0;

    // issue async loads for stage st covering k-range [k0, k0+64)
    auto do_load = [&](int st, int k0) {
        uint32_t aoff = sbase + (uint32_t)(st * SA_ST * 2);
        uint32_t boff = sbase + (uint32_t)((SB_BASE + st * SB_ST) * 2);
#pragma unroll
        for (int ii = 0; ii < 4; ii++) {
            int idx = tid + ii * 256;           // 0..1023
            // A: 128 rows x 8 chunks of 16B
            int ra = idx >> 3, ca = idx & 7;
            const char* asrc = (const char*)(g_x_f16 + (size_t)s_tok[ra] * H_DIM + k0) + ca * 16;
            CP_ASYNC16(aoff + (uint32_t)(ra * SA_LD + ca * 8) * 2, asrc);
            // B: 64 rows x 16 chunks of 16B
            int rb = idx >> 4, cb = idx & 15;
            const char* bsrc = (const char*)(wbase + (size_t)(k0 + rb) * H_DIM) + cb * 16;
            CP_ASYNC16(boff + (uint32_t)(rb * SB_LD + cb * 8) * 2, bsrc);
        }
        CP_COMMIT();
    };

    int wid = tid >> 5;
    int wm = wid & 3;   // 4 m-strips of 32 rows
    int wn = wid >> 2;  // 2 n-strips of 64 cols

    wmma::fragment<wmma::accumulator, 16, 16, 16, float> acc[2][4];
#pragma unroll
    for (int f = 0; f < 2; f++)
#pragma unroll
        for (int j = 0; j < 4; j++) wmma::fill_fragment(acc[f][j], 0.0f);

    do_load(0, 0);
    do_load(1, 64);

    for (int it = 0; it < 16; it++) {
        int st = it % N_STAGE;
        if (it == 15) { CP_WAIT(0); } else { CP_WAIT(1); }
        __syncthreads();
        // load two iterations ahead into the stage last read at it-1 (safe after the barrier)
        if (it + 2 < 16) do_load((it + 2) % N_STAGE, (it + 2) << 6);

        const __half* A0 = sA + st * SA_ST + (wm * 32) * SA_LD;
        const __half* B0 = sB + st * SB_ST + wn * 64;
#pragma unroll
        for (int ks = 0; ks < 4; ks++) {
            wmma::fragment<wmma::matrix_a, 16, 16, 16, __half, wmma::row_major> af[2];
            wmma::load_matrix_sync(af[0], A0 + ks * 16, SA_LD);
            wmma::load_matrix_sync(af[1], A0 + 16 * SA_LD + ks * 16, SA_LD);
#pragma unroll
            for (int j = 0; j < 4; j++) {
                wmma::fragment<wmma::matrix_b, 16, 16, 16, __half, wmma::row_major> bf;
                wmma::load_matrix_sync(bf, B0 + (ks * 16) * SB_LD + j * 16, SB_LD);
                wmma::mma_sync(acc[0][j], af[0], bf, acc[0][j]);
                wmma::mma_sync(acc[1][j], af[1], bf, acc[1][j]);
            }
        }
    }

    // epilogue: store 32x64 per warp
    float* yb = g_ybuf + (size_t)(row0 + wm * 32) * H_DIM + n0 + wn * 64;
#pragma unroll
    for (int f = 0; f < 2; f++)
#pragma unroll
        for (int j = 0; j < 4; j++)
            wmma::store_matrix_sync(yb + (size_t)(f * 16) * H_DIM + j * 16,
                                    acc[f][j], H_DIM, wmma::mem_row_major);
}

// ---------------- combine: out[b] = w0*y[p0] + w1*y[p1] ----------------
__global__ void combine_kernel(float* __restrict__ out) {
    int gid = blockIdx.x * blockDim.x + threadIdx.x;
    int b = gid >> 8;
    int c4 = gid & 255;
    float w0 = g_tok_w[2 * b];
    float w1 = g_tok_w[2 * b + 1];
    int p0 = g_pos[2 * b];
    int p1 = g_pos[2 * b + 1];
    float4 y0 = reinterpret_cast<const float4*>(g_ybuf + (size_t)p0 * H_DIM)[c4];
    float4 y1 = reinterpret_cast<const float4*>(g_ybuf + (size_t)p1 * H_DIM)[c4];
    float4 o;
    o.x = w0 * y0.x + w1 * y1.x;
    o.y = w0 * y0.y + w1 * y1.y;
    o.z = w0 * y0.z + w1 * y1.z;
    o.w = w0 * y0.w + w1 * y1.w;
    reinterpret_cast<float4*>(out + (size_t)b * H_DIM)[c4] = o;
}

// ---------------- launch ----------------
extern "C" void kernel_launch(void* const* d_in, const int* in_sizes, int n_in,
                              void* d_out, int out_size) {
    const float* x  = (const float*)d_in[0];
    const float* gw = (const float*)d_in[1];
    const float* ew = (const float*)d_in[2];
    float* out = (float*)d_out;

    cudaFuncSetAttribute(gemm_f16_kernel, cudaFuncAttributeMaxDynamicSharedMemorySize, SMEM_TOTAL);

    convert_kernel<<<2048, 256>>>(x, ew);
    gate_kernel<<<1024, 256>>>(x, gw);
    scatter_kernel<<<32, 256>>>();
    gemm_f16_kernel<<<dim3(137, 8), 256, SMEM_TOTAL>>>();
    combine_kernel<<<8192, 256>>>(out);
}